// round 7
// baseline (speedup 1.0000x reference)
#include <cuda_runtime.h>

// Problem constants (fixed by the reference).
#define BB   64
#define TT   512
#define VV   96
#define HH   1024
#define NCTA 128   // 32 k-chunks x 4 column tiles, co-resident (1 CTA/SM, 40KB smem)

// ---------------------------------------------------------------------------
// Scratch (device globals: allocation-free per harness rules)
// ---------------------------------------------------------------------------
__device__ float g_xproj[(size_t)BB * TT * HH];     // x @ Wxh + bh, [b][t][h]
__device__ float g_hs   [(size_t)BB * TT * HH];     // hidden states, [b][t][h]
__device__ float g_partial[32 * BB * HH];           // split-K partials [kc][b][j], 8MB
__device__ unsigned g_cnt = 0;
__device__ volatile unsigned g_gen = 0;

// ---------------------------------------------------------------------------
// Global software barrier — EXACTLY the R3/R6-proven version (incl. nanosleep).
// ---------------------------------------------------------------------------
__device__ __forceinline__ void gbar()
{
    __syncthreads();
    if (threadIdx.x == 0) {
        __threadfence();                      // release prior global stores
        unsigned g = g_gen;
        if (atomicAdd(&g_cnt, 1u) == NCTA - 1) {
            g_cnt = 0;
            __threadfence();
            g_gen = g + 1;
        } else {
            while (g_gen == g) { __nanosleep(64); }
        }
        __threadfence();                      // acquire
    }
    __syncthreads();
}

// ---------------------------------------------------------------------------
// Packed fp32x2 (Blackwell FFMA2). Two exact IEEE fp32 FMAs per instruction.
// ---------------------------------------------------------------------------
__device__ __forceinline__ unsigned long long splat2(float a)
{
    unsigned long long r;
    asm("mov.b64 %0, {%1, %1};" : "=l"(r) : "f"(a));
    return r;
}
__device__ __forceinline__ void ffma2(unsigned long long& d,
                                      unsigned long long a, unsigned long long b)
{
    asm("fma.rn.f32x2 %0, %1, %2, %0;" : "+l"(d) : "l"(a), "l"(b));
}

// ---------------------------------------------------------------------------
// Kernel 1: xproj[r][j] = sum_v x[r][v] * Wxh[v][j] + bh[j]   (unchanged, R3)
// ---------------------------------------------------------------------------
__global__ void __launch_bounds__(256) xproj_kernel(const float* __restrict__ x,
                                                    const float* __restrict__ Wxh,
                                                    const float* __restrict__ bh)
{
    __shared__ float sa[64][36];
    __shared__ float sw[32][64];

    const int tid = threadIdx.x;
    const int tx  = tid & 15;
    const int ty  = tid >> 4;
    const size_t row0 = (size_t)blockIdx.y * 64;
    const int jt  = blockIdx.x;

    float acc[4][4] = {};

    #pragma unroll 1
    for (int K0 = 0; K0 < 96; K0 += 32) {
        #pragma unroll
        for (int i = 0; i < 2; ++i) {
            int idx = tid + i * 256;
            int r = idx >> 3, k4 = (idx & 7) * 4;
            float4 v = *(const float4*)(x + (row0 + r) * 96 + K0 + k4);
            *(float4*)&sa[r][k4] = v;
        }
        #pragma unroll
        for (int i = 0; i < 2; ++i) {
            int idx = tid + i * 256;
            int kk = idx >> 4, j4 = (idx & 15) * 4;
            float4 v = *(const float4*)(Wxh + (size_t)(K0 + kk) * HH + jt * 64 + j4);
            *(float4*)&sw[kk][j4] = v;
        }
        __syncthreads();
        #pragma unroll 4
        for (int k = 0; k < 32; k += 4) {
            float ha[4][4], wa[4][4];
            #pragma unroll
            for (int i = 0; i < 4; ++i) {
                float4 v = *(const float4*)&sa[ty * 4 + i][k];
                ha[i][0] = v.x; ha[i][1] = v.y; ha[i][2] = v.z; ha[i][3] = v.w;
            }
            #pragma unroll
            for (int kk = 0; kk < 4; ++kk) {
                float4 v = *(const float4*)&sw[k + kk][tx * 4];
                wa[kk][0] = v.x; wa[kk][1] = v.y; wa[kk][2] = v.z; wa[kk][3] = v.w;
            }
            #pragma unroll
            for (int kk = 0; kk < 4; ++kk)
                #pragma unroll
                for (int i = 0; i < 4; ++i)
                    #pragma unroll
                    for (int j = 0; j < 4; ++j)
                        acc[i][j] += ha[i][kk] * wa[kk][j];
        }
        __syncthreads();
    }

    float4 bv = *(const float4*)(bh + jt * 64 + tx * 4);
    #pragma unroll
    for (int i = 0; i < 4; ++i) {
        float4 v = make_float4(acc[i][0] + bv.x, acc[i][1] + bv.y,
                               acc[i][2] + bv.z, acc[i][3] + bv.w);
        *(float4*)&g_xproj[(row0 + ty * 4 + i) * HH + jt * 64 + tx * 4] = v;
    }
}

// ---------------------------------------------------------------------------
// Kernel 2: persistent recurrence, FFMA2 geometry.
//   CTA bx: kc = bx>>2 (K chunk of 32), jt = bx&3 (256-col tile).
//   Phase 1: partial[kc][b][jt*256+j] = sum_{k in chunk} h[b][k] * Whh[k][j]
//            64x256 output, 8x8 thread tile (packed f32x2), K=32.
//            smem:fma balanced at 1 B/FMA -> ~4096 cyc/step.
//   Phase 2: h_t = tanh(xproj + sum over 32 kc partials), 1 float2/thread.
//   Whh slice (32x256, 32KB) persistent in smem; h tile 8KB; total 40KB.
//   Barrier structure identical to R3/R6 (proven).
// ---------------------------------------------------------------------------
__global__ void __launch_bounds__(256) rnn_kernel(const float* __restrict__ h0,
                                                  const float* __restrict__ Whh)
{
    __shared__ float sh[64][32];        // 8KB  h tile [b][k] (a-reads are broadcast)
    __shared__ float sw[32][256];       // 32KB Whh slice, persistent

    const int tid = threadIdx.x;
    const int bx  = blockIdx.x;
    const int kc  = bx >> 2;            // 0..31 (K chunk of 32)
    const int jt  = bx & 3;             // 0..3  (256-column tile)
    const int tx  = tid & 31;           // col group (8 cols each)
    const int ty  = tid >> 5;           // row group (8 rows each)

    // Preload Whh slice once: rows kc*32..+31, cols jt*256..+255.
    #pragma unroll
    for (int i = 0; i < 8; ++i) {
        int idx = tid + i * 256;
        int kk = idx >> 6, j4 = (idx & 63) * 4;
        float4 v = *(const float4*)(Whh + (size_t)(kc * 32 + kk) * HH + jt * 256 + j4);
        *(float4*)&sw[kk][j4] = v;
    }
    __syncthreads();

    // Phase-2 output coordinates (1 float2 per thread, fixed).
    const int o2  = bx * 256 + tid;     // 0..32767
    const int p2b = o2 >> 9;            // batch row
    const int p2j = (o2 & 511) * 2;     // column (even)

    for (int t = 0; t < TT; ++t) {
        const float* hb;
        size_t bstr;
        if (t == 0) { hb = h0;                          bstr = HH; }
        else        { hb = g_hs + (size_t)(t - 1) * HH; bstr = (size_t)TT * HH; }

        // ---- issue h-tile loads (64 rows x 32 k = 512 float4, 2/thread) ----
        float4 ra[2];
        #pragma unroll
        for (int i = 0; i < 2; ++i) {
            int idx = tid + i * 256;
            int bb = idx >> 3, c = idx & 7;
            ra[i] = __ldcg((const float4*)(hb + (size_t)bb * bstr + kc * 32 + c * 4));
        }
        // ---- prefetch phase-2 xproj (independent, read-only) ----
        float2 xp = __ldcg((const float2*)(g_xproj + ((size_t)p2b * TT + t) * HH + p2j));

        // ---- stage h tile ----
        #pragma unroll
        for (int i = 0; i < 2; ++i) {
            int idx = tid + i * 256;
            int bb = idx >> 3, c = idx & 7;
            *(float4*)&sh[bb][c * 4] = ra[i];
        }
        __syncthreads();

        // ---- compute: 8x8 tile, packed f32x2, K=32 ----
        unsigned long long acc[8][4] = {};   // [row][colpair] f32x2 (0 == {0,0})
        #pragma unroll
        for (int k = 0; k < 32; k += 4) {
            float4 a4[8];
            #pragma unroll
            for (int i = 0; i < 8; ++i)
                a4[i] = *(const float4*)&sh[ty * 8 + i][k];      // broadcast
            #pragma unroll
            for (int kk = 0; kk < 4; ++kk) {
                ulonglong2 w0 = *(const ulonglong2*)&sw[k + kk][tx * 8];
                ulonglong2 w1 = *(const ulonglong2*)&sw[k + kk][tx * 8 + 4];
                #pragma unroll
                for (int i = 0; i < 8; ++i) {
                    unsigned long long s = splat2(((const float*)&a4[i])[kk]);
                    ffma2(acc[i][0], s, w0.x);
                    ffma2(acc[i][1], s, w0.y);
                    ffma2(acc[i][2], s, w1.x);
                    ffma2(acc[i][3], s, w1.y);
                }
            }
        }
        __syncthreads();   // sh reusable next step only after all reads done

        // ---- publish split-K partials: rows ty*8..+7, cols jt*256+tx*8..+7 ----
        {
            float* pp = g_partial + (size_t)kc * (BB * HH) + jt * 256 + tx * 8;
            #pragma unroll
            for (int i = 0; i < 8; ++i) {
                int b = ty * 8 + i;
                *(ulonglong2*)&pp[(size_t)b << 10]       = make_ulonglong2(acc[i][0], acc[i][1]);
                *(ulonglong2*)&pp[((size_t)b << 10) + 4] = make_ulonglong2(acc[i][2], acc[i][3]);
            }
        }

        gbar();

        // ---- phase 2: reduce 32 partials + xproj, tanh, write h_t ----
        {
            float sx = xp.x, sy = xp.y;
            const float* pb = g_partial + (size_t)(p2b << 10) + p2j;
            #pragma unroll
            for (int c = 0; c < 32; ++c) {
                float2 pv = __ldcg((const float2*)(pb + (size_t)c * (BB * HH)));
                sx += pv.x; sy += pv.y;
            }
            float2 o = make_float2(tanhf(sx), tanhf(sy));
            *(float2*)&g_hs[((size_t)p2b * TT + t) * HH + p2j] = o;
        }

        gbar();
    }
}

// ---------------------------------------------------------------------------
// Kernel 3: logits[r][v] = sum_k hs[r][k] * Wl[v][k] + bl[v]  (unchanged, R3)
// ---------------------------------------------------------------------------
__global__ void __launch_bounds__(256) logits_kernel(const float* __restrict__ Wl,
                                                     const float* __restrict__ bl,
                                                     float* __restrict__ out)
{
    __shared__ float sa [64][36];
    __shared__ float swl[32][100];

    const int tid = threadIdx.x;
    const int tx  = tid & 15;
    const int ty  = tid >> 4;
    const size_t row0 = (size_t)blockIdx.x * 64;
    const int v0  = tx * 6;

    float acc[4][6] = {};

    #pragma unroll 1
    for (int K0 = 0; K0 < HH; K0 += 32) {
        #pragma unroll
        for (int i = 0; i < 2; ++i) {
            int idx = tid + i * 256;
            int r = idx >> 3, k4 = (idx & 7) * 4;
            float4 v = *(const float4*)(g_hs + (row0 + r) * HH + K0 + k4);
            *(float4*)&sa[r][k4] = v;
        }
        #pragma unroll
        for (int i = 0; i < 3; ++i) {
            int idx = tid + i * 256;
            int vv = idx >> 3, k4 = (idx & 7) * 4;
            float4 v = *(const float4*)(Wl + (size_t)vv * HH + K0 + k4);
            swl[k4 + 0][vv] = v.x;
            swl[k4 + 1][vv] = v.y;
            swl[k4 + 2][vv] = v.z;
            swl[k4 + 3][vv] = v.w;
        }
        __syncthreads();
        #pragma unroll 4
        for (int k = 0; k < 32; ++k) {
            float a0 = sa[ty * 4 + 0][k];
            float a1 = sa[ty * 4 + 1][k];
            float a2 = sa[ty * 4 + 2][k];
            float a3 = sa[ty * 4 + 3][k];
            #pragma unroll
            for (int j = 0; j < 6; ++j) {
                float w = swl[k][v0 + j];
                acc[0][j] += a0 * w;
                acc[1][j] += a1 * w;
                acc[2][j] += a2 * w;
                acc[3][j] += a3 * w;
            }
        }
        __syncthreads();
    }

    #pragma unroll
    for (int i = 0; i < 4; ++i)
        #pragma unroll
        for (int j = 0; j < 6; ++j)
            out[(row0 + ty * 4 + i) * VV + v0 + j] = acc[i][j] + bl[v0 + j];
}

// ---------------------------------------------------------------------------
// Kernel 4: h_last = hs[:, T-1, :]
// ---------------------------------------------------------------------------
__global__ void __launch_bounds__(256) hlast_kernel(float* __restrict__ out)
{
    int i = blockIdx.x * 256 + threadIdx.x;
    int b = i >> 10, j = i & 1023;
    out[i] = g_hs[((size_t)b * TT + (TT - 1)) * HH + j];
}

// ---------------------------------------------------------------------------
extern "C" void kernel_launch(void* const* d_in, const int* in_sizes, int n_in,
                              void* d_out, int out_size)
{
    const float* x   = (const float*)d_in[0];
    const float* h0  = (const float*)d_in[1];
    const float* Wxh = (const float*)d_in[2];
    const float* Whh = (const float*)d_in[3];
    const float* bh  = (const float*)d_in[4];
    const float* Wl  = (const float*)d_in[5];
    const float* bl  = (const float*)d_in[6];
    float* out = (float*)d_out;
    (void)in_sizes; (void)n_in;

    xproj_kernel <<<dim3(16, (BB * TT) / 64), 256>>>(x, Wxh, bh);
    rnn_kernel   <<<NCTA, 256>>>(h0, Whh);
    logits_kernel<<<(BB * TT) / 64, 256>>>(Wl, bl, out);

    const size_t logits_elems = (size_t)BB * TT * VV;
    if ((size_t)out_size >= logits_elems + (size_t)BB * HH)
        hlast_kernel<<<(BB * HH) / 256, 256>>>(out + logits_elems);
}

// round 8
// speedup vs baseline: 1.1930x; 1.1930x over previous
#include <cuda_runtime.h>

// Problem constants (fixed by the reference).
#define BB   64
#define TT   512
#define VV   96
#define HH   1024
#define NCTA 128   // 16 k-chunks x 8 column tiles, co-resident (1 CTA/SM, 48KB smem)

// ---------------------------------------------------------------------------
// Scratch (device globals: allocation-free per harness rules)
// ---------------------------------------------------------------------------
__device__ float g_xproj[(size_t)BB * TT * HH];     // x @ Wxh + bh, [b][t][h]
__device__ float g_hs   [(size_t)BB * TT * HH];     // hidden states, [b][t][h]
__device__ float g_partial[16 * BB * HH];           // split-K partials [kc][b][j], 4MB
__device__ unsigned g_cnt = 0;
__device__ volatile unsigned g_gen = 0;

// ---------------------------------------------------------------------------
// Global software barrier — EXACTLY the R3/R6-proven version (incl. nanosleep).
// ---------------------------------------------------------------------------
__device__ __forceinline__ void gbar()
{
    __syncthreads();
    if (threadIdx.x == 0) {
        __threadfence();                      // release prior global stores
        unsigned g = g_gen;
        if (atomicAdd(&g_cnt, 1u) == NCTA - 1) {
            g_cnt = 0;
            __threadfence();
            g_gen = g + 1;
        } else {
            while (g_gen == g) { __nanosleep(64); }
        }
        __threadfence();                      // acquire
    }
    __syncthreads();
}

// ---------------------------------------------------------------------------
// Packed fp32x2 (Blackwell FFMA2). Two exact IEEE fp32 FMAs per instruction.
// ---------------------------------------------------------------------------
__device__ __forceinline__ unsigned long long splat2(float a)
{
    unsigned long long r;
    asm("mov.b64 %0, {%1, %1};" : "=l"(r) : "f"(a));
    return r;
}
__device__ __forceinline__ void ffma2(unsigned long long& d,
                                      unsigned long long a, unsigned long long b)
{
    asm("fma.rn.f32x2 %0, %1, %2, %0;" : "+l"(d) : "l"(a), "l"(b));
}

// ---------------------------------------------------------------------------
// Kernel 1: xproj[r][j] = sum_v x[r][v] * Wxh[v][j] + bh[j]   (unchanged, R3)
// ---------------------------------------------------------------------------
__global__ void __launch_bounds__(256) xproj_kernel(const float* __restrict__ x,
                                                    const float* __restrict__ Wxh,
                                                    const float* __restrict__ bh)
{
    __shared__ float sa[64][36];
    __shared__ float sw[32][64];

    const int tid = threadIdx.x;
    const int tx  = tid & 15;
    const int ty  = tid >> 4;
    const size_t row0 = (size_t)blockIdx.y * 64;
    const int jt  = blockIdx.x;

    float acc[4][4] = {};

    #pragma unroll 1
    for (int K0 = 0; K0 < 96; K0 += 32) {
        #pragma unroll
        for (int i = 0; i < 2; ++i) {
            int idx = tid + i * 256;
            int r = idx >> 3, k4 = (idx & 7) * 4;
            float4 v = *(const float4*)(x + (row0 + r) * 96 + K0 + k4);
            *(float4*)&sa[r][k4] = v;
        }
        #pragma unroll
        for (int i = 0; i < 2; ++i) {
            int idx = tid + i * 256;
            int kk = idx >> 4, j4 = (idx & 15) * 4;
            float4 v = *(const float4*)(Wxh + (size_t)(K0 + kk) * HH + jt * 64 + j4);
            *(float4*)&sw[kk][j4] = v;
        }
        __syncthreads();
        #pragma unroll 4
        for (int k = 0; k < 32; k += 4) {
            float ha[4][4], wa[4][4];
            #pragma unroll
            for (int i = 0; i < 4; ++i) {
                float4 v = *(const float4*)&sa[ty * 4 + i][k];
                ha[i][0] = v.x; ha[i][1] = v.y; ha[i][2] = v.z; ha[i][3] = v.w;
            }
            #pragma unroll
            for (int kk = 0; kk < 4; ++kk) {
                float4 v = *(const float4*)&sw[k + kk][tx * 4];
                wa[kk][0] = v.x; wa[kk][1] = v.y; wa[kk][2] = v.z; wa[kk][3] = v.w;
            }
            #pragma unroll
            for (int kk = 0; kk < 4; ++kk)
                #pragma unroll
                for (int i = 0; i < 4; ++i)
                    #pragma unroll
                    for (int j = 0; j < 4; ++j)
                        acc[i][j] += ha[i][kk] * wa[kk][j];
        }
        __syncthreads();
    }

    float4 bv = *(const float4*)(bh + jt * 64 + tx * 4);
    #pragma unroll
    for (int i = 0; i < 4; ++i) {
        float4 v = make_float4(acc[i][0] + bv.x, acc[i][1] + bv.y,
                               acc[i][2] + bv.z, acc[i][3] + bv.w);
        *(float4*)&g_xproj[(row0 + ty * 4 + i) * HH + jt * 64 + tx * 4] = v;
    }
}

// ---------------------------------------------------------------------------
// Kernel 2: persistent recurrence — FFMA2, kc=16/jt=8 geometry.
//   CTA bx: kc = bx>>3 (K chunk of 64), jt = bx&7 (128-col tile).
//   Phase 1: 64x128 output tile, 4 rows x (4+4 strided) cols per thread,
//            packed f32x2 accumulators. Compute-bound: 4096 cyc fma,
//            ~2.2K cyc smem.
//   Phase 2: h_t = tanh(xproj + sum of 16 partials), 1 float2/thread.
//   Whh slice 64x128 (32KB) persistent in smem; h tile 16KB swizzled.
//   Barrier structure identical to R3/R6 (proven).
// ---------------------------------------------------------------------------
__global__ void __launch_bounds__(256) rnn_kernel(const float* __restrict__ h0,
                                                  const float* __restrict__ Whh)
{
    __shared__ float sh[64][64];        // 16KB h tile [b][k], float4 cols XOR-(row&15)
    __shared__ float sw[64][128];       // 32KB Whh slice [k][j], persistent

    const int tid = threadIdx.x;
    const int bx  = blockIdx.x;
    const int kc  = bx >> 3;            // 0..15 (K chunk of 64)
    const int jt  = bx & 7;             // 0..7  (128-column tile)
    const int tx  = tid & 15;           // col group: cols {tx*4..+3} and {64+tx*4..+3}
    const int ty  = tid >> 4;           // row group: rows ty*4..+3

    // Preload Whh slice once: rows kc*64..+63, cols jt*128..+127.
    #pragma unroll
    for (int i = 0; i < 8; ++i) {
        int idx = tid + i * 256;
        int kk = idx >> 5, j4 = (idx & 31) * 4;
        float4 v = *(const float4*)(Whh + (size_t)(kc * 64 + kk) * HH + jt * 128 + j4);
        *(float4*)&sw[kk][j4] = v;
    }
    __syncthreads();

    // Phase-2 output coordinates (1 float2 per thread, fixed; R7-proven mapping).
    const int o2  = bx * 256 + tid;     // 0..32767
    const int p2b = o2 >> 9;            // batch row
    const int p2j = (o2 & 511) * 2;     // column (even)

    for (int t = 0; t < TT; ++t) {
        const float* hb;
        size_t bstr;
        if (t == 0) { hb = h0;                          bstr = HH; }
        else        { hb = g_hs + (size_t)(t - 1) * HH; bstr = (size_t)TT * HH; }

        // ---- issue h-tile loads: 64 rows x 64 k = 1024 float4, 4/thread ----
        float4 ra[4];
        #pragma unroll
        for (int i = 0; i < 4; ++i) {
            int idx = tid + i * 256;
            int bb = idx >> 4, c = idx & 15;
            ra[i] = __ldcg((const float4*)(hb + (size_t)bb * bstr + kc * 64 + c * 4));
        }
        // ---- prefetch phase-2 xproj (independent, read-only) ----
        float2 xp = __ldcg((const float2*)(g_xproj + ((size_t)p2b * TT + t) * HH + p2j));

        // ---- stage h tile (XOR swizzle, R6-proven pattern) ----
        #pragma unroll
        for (int i = 0; i < 4; ++i) {
            int idx = tid + i * 256;
            int bb = idx >> 4, c = idx & 15;
            *(float4*)&sh[bb][((c ^ (bb & 15)) << 2)] = ra[i];
        }
        __syncthreads();

        // ---- compute: 4 rows x 8 cols (two strided float4 groups), f32x2 ----
        unsigned long long acc[4][4] = {};   // [row][pair]: pairs 0,1 = cols tx*4..+3;
                                             //              pairs 2,3 = cols 64+tx*4..+3
        #pragma unroll 4
        for (int k = 0; k < 64; k += 4) {
            const int c4 = k >> 2;
            float4 a4[4];
            #pragma unroll
            for (int i = 0; i < 4; ++i) {
                int row = ty * 4 + i;
                a4[i] = *(const float4*)&sh[row][((c4 ^ (row & 15)) << 2)];
            }
            #pragma unroll
            for (int kk = 0; kk < 4; ++kk) {
                ulonglong2 w0 = *(const ulonglong2*)&sw[k + kk][tx * 4];       // cols tx*4..+3
                ulonglong2 w1 = *(const ulonglong2*)&sw[k + kk][64 + tx * 4];  // cols 64+tx*4..+3
                #pragma unroll
                for (int i = 0; i < 4; ++i) {
                    unsigned long long s = splat2(((const float*)&a4[i])[kk]);
                    ffma2(acc[i][0], s, w0.x);
                    ffma2(acc[i][1], s, w0.y);
                    ffma2(acc[i][2], s, w1.x);
                    ffma2(acc[i][3], s, w1.y);
                }
            }
        }
        __syncthreads();   // sh reusable next step only after all reads done

        // ---- publish split-K partials ----
        {
            float* pp = g_partial + (size_t)kc * (BB * HH) + jt * 128;
            #pragma unroll
            for (int i = 0; i < 4; ++i) {
                int b = ty * 4 + i;
                *(ulonglong2*)&pp[((size_t)b << 10) + tx * 4]      = make_ulonglong2(acc[i][0], acc[i][1]);
                *(ulonglong2*)&pp[((size_t)b << 10) + 64 + tx * 4] = make_ulonglong2(acc[i][2], acc[i][3]);
            }
        }

        gbar();

        // ---- phase 2: reduce 16 partials + xproj, tanh, write h_t ----
        {
            float sx = xp.x, sy = xp.y;
            const float* pb = g_partial + (size_t)(p2b << 10) + p2j;
            #pragma unroll
            for (int c = 0; c < 16; ++c) {
                float2 pv = __ldcg((const float2*)(pb + (size_t)c * (BB * HH)));
                sx += pv.x; sy += pv.y;
            }
            float2 o = make_float2(tanhf(sx), tanhf(sy));
            *(float2*)&g_hs[((size_t)p2b * TT + t) * HH + p2j] = o;
        }

        gbar();
    }
}

// ---------------------------------------------------------------------------
// Kernel 3: logits[r][v] = sum_k hs[r][k] * Wl[v][k] + bl[v]  (unchanged, R3)
// ---------------------------------------------------------------------------
__global__ void __launch_bounds__(256) logits_kernel(const float* __restrict__ Wl,
                                                     const float* __restrict__ bl,
                                                     float* __restrict__ out)
{
    __shared__ float sa [64][36];
    __shared__ float swl[32][100];

    const int tid = threadIdx.x;
    const int tx  = tid & 15;
    const int ty  = tid >> 4;
    const size_t row0 = (size_t)blockIdx.x * 64;
    const int v0  = tx * 6;

    float acc[4][6] = {};

    #pragma unroll 1
    for (int K0 = 0; K0 < HH; K0 += 32) {
        #pragma unroll
        for (int i = 0; i < 2; ++i) {
            int idx = tid + i * 256;
            int r = idx >> 3, k4 = (idx & 7) * 4;
            float4 v = *(const float4*)(g_hs + (row0 + r) * HH + K0 + k4);
            *(float4*)&sa[r][k4] = v;
        }
        #pragma unroll
        for (int i = 0; i < 3; ++i) {
            int idx = tid + i * 256;
            int vv = idx >> 3, k4 = (idx & 7) * 4;
            float4 v = *(const float4*)(Wl + (size_t)vv * HH + K0 + k4);
            swl[k4 + 0][vv] = v.x;
            swl[k4 + 1][vv] = v.y;
            swl[k4 + 2][vv] = v.z;
            swl[k4 + 3][vv] = v.w;
        }
        __syncthreads();
        #pragma unroll 4
        for (int k = 0; k < 32; ++k) {
            float a0 = sa[ty * 4 + 0][k];
            float a1 = sa[ty * 4 + 1][k];
            float a2 = sa[ty * 4 + 2][k];
            float a3 = sa[ty * 4 + 3][k];
            #pragma unroll
            for (int j = 0; j < 6; ++j) {
                float w = swl[k][v0 + j];
                acc[0][j] += a0 * w;
                acc[1][j] += a1 * w;
                acc[2][j] += a2 * w;
                acc[3][j] += a3 * w;
            }
        }
        __syncthreads();
    }

    #pragma unroll
    for (int i = 0; i < 4; ++i)
        #pragma unroll
        for (int j = 0; j < 6; ++j)
            out[(row0 + ty * 4 + i) * VV + v0 + j] = acc[i][j] + bl[v0 + j];
}

// ---------------------------------------------------------------------------
// Kernel 4: h_last = hs[:, T-1, :]
// ---------------------------------------------------------------------------
__global__ void __launch_bounds__(256) hlast_kernel(float* __restrict__ out)
{
    int i = blockIdx.x * 256 + threadIdx.x;
    int b = i >> 10, j = i & 1023;
    out[i] = g_hs[((size_t)b * TT + (TT - 1)) * HH + j];
}

// ---------------------------------------------------------------------------
extern "C" void kernel_launch(void* const* d_in, const int* in_sizes, int n_in,
                              void* d_out, int out_size)
{
    const float* x   = (const float*)d_in[0];
    const float* h0  = (const float*)d_in[1];
    const float* Wxh = (const float*)d_in[2];
    const float* Whh = (const float*)d_in[3];
    const float* bh  = (const float*)d_in[4];
    const float* Wl  = (const float*)d_in[5];
    const float* bl  = (const float*)d_in[6];
    float* out = (float*)d_out;
    (void)in_sizes; (void)n_in;

    xproj_kernel <<<dim3(16, (BB * TT) / 64), 256>>>(x, Wxh, bh);
    rnn_kernel   <<<NCTA, 256>>>(h0, Whh);
    logits_kernel<<<(BB * TT) / 64, 256>>>(Wl, bl, out);

    const size_t logits_elems = (size_t)BB * TT * VV;
    if ((size_t)out_size >= logits_elems + (size_t)BB * HH)
        hlast_kernel<<<(BB * HH) / 256, 256>>>(out + logits_elems);
}